// round 7
// baseline (speedup 1.0000x reference)
#include <cuda_runtime.h>
#include <math_constants.h>

#define BATCH 16
#define H 1024
#define W 1024
#define HW (H * W)
#define TOPKN 512
#define CAP 131072

static __device__ int g_candcount[BATCH];
static __device__ unsigned long long g_cands[BATCH][CAP];

__device__ __forceinline__ unsigned int ford(float f) {
    unsigned int u = __float_as_uint(f);
    return (u & 0x80000000u) ? ~u : (u | 0x80000000u);
}
__device__ __forceinline__ float finv(unsigned int u) {
    u = (u & 0x80000000u) ? (u & 0x7fffffffu) : ~u;
    return __uint_as_float(u);
}

// ---------------------------------------------------------------------------
// Fused kernel: per 128x32 output tile
//   phase 1: Shi-Tomasi resp for 144x46 region (output + 7 NMS halo) into smem
//            via warp-shuffle pipeline (6 warps x 24 cols), exact int math
//   phase 2: 3x3-max table m3, prune (v >= m3 center), verify survivors with
//            the 5x5 stride-3 grid of m3 (== exact 15x15 max), emit candidates
// ---------------------------------------------------------------------------
#define OW 128
#define OH 32
#define RW 144                 // resp cols per block (OW + 14 + 2 pad)
#define RH 46                  // resp rows per block (OH + 14)
#define SR_STRIDE 145
#define M3_STRIDE 144
#define SURVCAP 1536
#define FUSED_SMEM (RH * SR_STRIDE * 4 + RH * M3_STRIDE * 4 + SURVCAP * 8)

__global__ __launch_bounds__(192) void fused_kernel(const float* __restrict__ im) {
    extern __shared__ char smem_raw[];
    float* sresp = (float*)smem_raw;                     // [RH][SR_STRIDE]
    float* m3    = sresp + RH * SR_STRIDE;               // [RH][M3_STRIDE] rows 1..44
    float* sv    = m3 + RH * M3_STRIDE;                  // [SURVCAP]
    int*   srs   = (int*)(sv + SURVCAP);                 // [SURVCAP]
    __shared__ int scount;

    const int b  = blockIdx.z;
    const int X0 = blockIdx.x * OW;
    const int Y0 = blockIdx.y * OH;
    const int t  = threadIdx.x;
    const int wid = t >> 5, lane = t & 31;
    const int cc  = wid * 24 + lane - 4;        // resp-local col this lane outputs
    const int gc  = X0 - 7 + cc;                // global image col for this lane
    const bool colin   = ((unsigned)gc < W);
    const bool outlane = (lane >= 4) && (lane < 28);
    const float* imb = im + (size_t)b * HW;

    if (t == 0) scount = 0;

    // ---- phase 1: resp into smem ----
    const int y0res = Y0 - 7;
    auto loadrow = [&](int rr) -> int {
        return ((unsigned)rr < H && colin)
                   ? __float2int_rd(imb[(size_t)rr * W + gc] * 255.0f)
                   : 0;
    };

    int qm = loadrow(y0res - 4);
    int qc_ = loadrow(y0res - 3);
    int qp = loadrow(y0res - 2);
    int qn = loadrow(y0res - 1);

    int rA[7], rB[7], rC[7];
#pragma unroll
    for (int j = 0; j < 7; j++) { rA[j] = 0; rB[j] = 0; rC[j] = 0; }
    int sA = 0, sB = 0, sC = 0;

    for (int i = 0; i < RH + 6; i++) {
        const int pr = y0res - 3 + i;           // product row
        const int qn2 = loadrow(pr + 3);

        int A = 0, Bv = 0, C = 0;
        {
            int v = qm + 2 * qc_ + qp;
            int d = qp - qm;
            int gx = __shfl_down_sync(0xffffffffu, v, 1) -
                     __shfl_up_sync(0xffffffffu, v, 1);
            int gy = __shfl_up_sync(0xffffffffu, d, 1) + 2 * d +
                     __shfl_down_sync(0xffffffffu, d, 1);
            if (((unsigned)pr < H) & colin) {
                A = gx * gx; Bv = gx * gy; C = gy * gy;
            }
        }

        int hA, hB, hC;
        {
            int s1 = A + __shfl_down_sync(0xffffffffu, A, 1);
            int s2 = s1 + __shfl_down_sync(0xffffffffu, s1, 2);
            hA = __shfl_up_sync(0xffffffffu, s2, 3) +
                 __shfl_down_sync(0xffffffffu, s2, 1) -
                 __shfl_down_sync(0xffffffffu, A, 4);
        }
        {
            int s1 = Bv + __shfl_down_sync(0xffffffffu, Bv, 1);
            int s2 = s1 + __shfl_down_sync(0xffffffffu, s1, 2);
            hB = __shfl_up_sync(0xffffffffu, s2, 3) +
                 __shfl_down_sync(0xffffffffu, s2, 1) -
                 __shfl_down_sync(0xffffffffu, Bv, 4);
        }
        {
            int s1 = C + __shfl_down_sync(0xffffffffu, C, 1);
            int s2 = s1 + __shfl_down_sync(0xffffffffu, s1, 2);
            hC = __shfl_up_sync(0xffffffffu, s2, 3) +
                 __shfl_down_sync(0xffffffffu, s2, 1) -
                 __shfl_down_sync(0xffffffffu, C, 4);
        }

        // vertical sliding 7-sum, ring depth 7
        sA += hA - rA[0];
        sB += hB - rB[0];
        sC += hC - rC[0];
#pragma unroll
        for (int j = 0; j < 6; j++) { rA[j] = rA[j + 1]; rB[j] = rB[j + 1]; rC[j] = rC[j + 1]; }
        rA[6] = hA; rB[6] = hB; rC[6] = hC;

        if (i >= 6) {
            const int rr = i - 6;               // resp-local row
            const int gr = y0res + rr;          // global row
            float fa = (float)sA, fc = (float)sC, fb = (float)sB;
            float dd = __fsub_rn(fa, fc);
            float s  = __fadd_rn(__fmul_rn(dd, dd), __fmul_rn(__fmul_rn(4.0f, fb), fb));
            float resp = 0.5f * __fsub_rn(__fadd_rn(fa, fc), __fsqrt_rn(s));
            if (outlane) {
                float val = (((unsigned)gr < H) & colin) ? resp : -CUDART_INF_F;
                sresp[rr * SR_STRIDE + cc] = val;
            }
        }

        qm = qc_; qc_ = qp; qp = qn; qn = qn2;
    }
    __syncthreads();

    // ---- phase 2a: m3 = 3x3 max of resp (rows 1..44, cols 1..142) ----
    for (int i = t; i < 44 * 142; i += 192) {
        int rr = 1 + i / 142, cx = 1 + i % 142;
        const float* p0 = &sresp[(rr - 1) * SR_STRIDE + cx - 1];
        const float* p1 = p0 + SR_STRIDE;
        const float* p2 = p1 + SR_STRIDE;
        float m = fmaxf(fmaxf(fmaxf(p0[0], p0[1]), fmaxf(p0[2], p1[0])),
                        fmaxf(fmaxf(p1[1], p1[2]), fmaxf(fmaxf(p2[0], p2[1]), p2[2])));
        m3[rr * M3_STRIDE + cx] = m;
    }
    __syncthreads();

    // ---- phase 2b: prune with 3x3 test ----
    for (int i = t; i < OH * OW; i += 192) {
        int r = 7 + (i >> 7), c = 7 + (i & 127);
        float v = sresp[r * SR_STRIDE + c];
        if (v >= m3[r * M3_STRIDE + c]) {
            int s = atomicAdd(&scount, 1);
            if (s < SURVCAP) { sv[s] = v; srs[s] = (r << 8) | c; }
        }
    }
    __syncthreads();

    // ---- phase 2c: verify survivors with 5x5 grid of m3 (exact 15x15 max) ----
    int sc = scount < SURVCAP ? scount : SURVCAP;
    for (int i = t; i < sc; i += 192) {
        float v = sv[i];
        int rc = srs[i];
        int r = rc >> 8, c = rc & 255;
        const float* mb = &m3[(r - 6) * M3_STRIDE + (c - 6)];
        float m = -CUDART_INF_F;
#pragma unroll
        for (int di = 0; di < 5; di++) {
            const float* row = mb + di * 3 * M3_STRIDE;
#pragma unroll
            for (int dj = 0; dj < 5; dj++) m = fmaxf(m, row[dj * 3]);
        }
        if (v >= m) {
            unsigned int idx = (unsigned)((Y0 + r - 7) * W + (X0 + c - 7));
            unsigned long long key =
                ((unsigned long long)ford(v) << 32) | (unsigned int)(~idx);
            int slot = atomicAdd(&g_candcount[b], 1);
            if (slot < CAP) g_cands[b][slot] = key;
        }
    }
}

// ---------------------------------------------------------------------------
// topk: max-scan (-> thresh = 0.3*max), exact top-512 via 6-pass histogram
// radix select, bitonic sort, apply threshold at output, self-reset counter.
// ---------------------------------------------------------------------------
__global__ __launch_bounds__(512) void topk_kernel(float* __restrict__ out, int write_coords) {
    const int b = blockIdx.x;
    const int t = threadIdx.x;
    __shared__ int hist[2048];
    __shared__ int s_sth[512];
    __shared__ int s_ws[16];
    __shared__ unsigned int s_mx[16];
    __shared__ unsigned long long skeys[TOPKN];
    __shared__ unsigned long long s_prefix;
    __shared__ int s_need;
    __shared__ int s_cnt;

    int n = g_candcount[b]; if (n > CAP) n = CAP;
    int Kb = n < TOPKN ? n : TOPKN;
    const unsigned long long* cb = g_cands[b];

    // max value scan -> threshold
    unsigned int hx = 0;
    for (int i = t; i < n; i += 512) {
        unsigned int hi = (unsigned int)(cb[i] >> 32);
        if (hi > hx) hx = hi;
    }
#pragma unroll
    for (int o = 16; o; o >>= 1) {
        unsigned int v = __shfl_xor_sync(0xffffffffu, hx, o);
        if (v > hx) hx = v;
    }
    if ((t & 31) == 0) s_mx[t >> 5] = hx;
    __syncthreads();
    unsigned int hmax = s_mx[0];
#pragma unroll
    for (int w = 1; w < 16; w++) if (s_mx[w] > hmax) hmax = s_mx[w];
    const float thresh = 0.3f * finv(hmax);

    unsigned long long T = 0ull;
    if (Kb > 0) {
        if (t == 0) { s_prefix = 0ull; s_need = Kb; }
        __syncthreads();
        const int sh_arr[6] = {53, 42, 31, 20, 9, 0};
#pragma unroll 1
        for (int pass = 0; pass < 6; pass++) {
            const int sh = sh_arr[pass];
            const int width = (pass < 5) ? 11 : 9;
            const unsigned int mask = (1u << width) - 1u;
            for (int i = t; i < 2048; i += 512) hist[i] = 0;
            __syncthreads();
            unsigned long long pref = s_prefix;
            const int hb = sh + width;
            const bool all = (pass == 0);
            const unsigned long long ph = all ? 0ull : (pref >> hb);
            for (int i = t; i < n; i += 512) {
                unsigned long long k = cb[i];
                if (all || (k >> hb) == ph)
                    atomicAdd(&hist[(int)((k >> sh) & mask)], 1);
            }
            __syncthreads();
            int sth = hist[4 * t] + hist[4 * t + 1] + hist[4 * t + 2] + hist[4 * t + 3];
            s_sth[t] = sth;
            int wsum = sth;
#pragma unroll
            for (int o = 16; o; o >>= 1) wsum += __shfl_xor_sync(0xffffffffu, wsum, o);
            if ((t & 31) == 0) s_ws[t >> 5] = wsum;
            __syncthreads();
            if (t == 0) {
                int need = s_need, cum = 0, w, th, bin;
                for (w = 15; w > 0; w--) { int v = s_ws[w]; if (cum + v >= need) break; cum += v; }
                for (th = 31; th > 0; th--) { int v = s_sth[w * 32 + th]; if (cum + v >= need) break; cum += v; }
                int base = (w * 32 + th) * 4;
                for (bin = 3; bin > 0; bin--) { int v = hist[base + bin]; if (cum + v >= need) break; cum += v; }
                s_need = need - cum;
                s_prefix = pref | ((unsigned long long)(base + bin) << sh);
            }
            __syncthreads();
        }
        T = s_prefix;
    }

    if (t == 0) s_cnt = 0;
    __syncthreads();
    if (Kb > 0) {
        for (int i = t; i < n; i += 512) {
            unsigned long long k = cb[i];
            if (k >= T) {
                int p = atomicAdd(&s_cnt, 1);
                if (p < TOPKN) skeys[p] = k;
            }
        }
    }
    __syncthreads();
    int m = s_cnt < TOPKN ? s_cnt : TOPKN;
    if (t >= m) skeys[t] = 0ull;
    __syncthreads();

    for (int k = 2; k <= TOPKN; k <<= 1) {
        for (int j = k >> 1; j > 0; j >>= 1) {
            int ixj = t ^ j;
            if (ixj > t) {
                unsigned long long a = skeys[t], c = skeys[ixj];
                bool sw = ((t & k) == 0) ? (a < c) : (a > c);
                if (sw) { skeys[t] = c; skeys[ixj] = a; }
            }
            __syncthreads();
        }
    }

    unsigned long long key = skeys[t];
    bool valid = (key != 0ull) && (finv((unsigned int)(key >> 32)) >= thresh);
    if (valid) {
        unsigned int idx = ~((unsigned int)key);
        out[(size_t)b * HW + idx] = 1.0f;
        if (write_coords) {
            float* coords = out + (size_t)BATCH * HW;
            coords[((size_t)b * TOPKN + t) * 2 + 0] = (float)(idx >> 10);
            coords[((size_t)b * TOPKN + t) * 2 + 1] = (float)(idx & 1023u);
        }
    } else if (write_coords) {
        float* coords = out + (size_t)BATCH * HW;
        coords[((size_t)b * TOPKN + t) * 2 + 0] = -1.0f;
        coords[((size_t)b * TOPKN + t) * 2 + 1] = -1.0f;
    }

    __syncthreads();
    if (t == 0) g_candcount[b] = 0;   // self-reset for next graph replay
}

extern "C" void kernel_launch(void* const* d_in, const int* in_sizes, int n_in,
                              void* d_out, int out_size) {
    const float* im = (const float*)d_in[0];
    float* out = (float*)d_out;

    // Idempotent, called every invocation (no static guards per harness rules)
    cudaFuncSetAttribute(fused_kernel,
                         cudaFuncAttributeMaxDynamicSharedMemorySize, FUSED_SMEM);

    cudaMemsetAsync(d_out, 0, (size_t)out_size * sizeof(float));

    dim3 grid(W / OW, H / OH, BATCH);
    fused_kernel<<<grid, 192, FUSED_SMEM>>>(im);

    int wc = (out_size >= BATCH * HW + BATCH * TOPKN * 2) ? 1 : 0;
    topk_kernel<<<BATCH, 512>>>(out, wc);
}

// round 8
// speedup vs baseline: 1.0619x; 1.0619x over previous
#include <cuda_runtime.h>
#include <math_constants.h>

#define BATCH 16
#define H 1024
#define W 1024
#define HW (H * W)
#define TOPKN 512
#define CAP 131072

static __device__ int g_candcount[BATCH];
static __device__ unsigned long long g_cands[BATCH][CAP];

__device__ __forceinline__ unsigned int ford(float f) {
    unsigned int u = __float_as_uint(f);
    return (u & 0x80000000u) ? ~u : (u | 0x80000000u);
}
__device__ __forceinline__ float finv(unsigned int u) {
    u = (u & 0x80000000u) ? (u & 0x7fffffffu) : ~u;
    return __uint_as_float(u);
}

// ---------------------------------------------------------------------------
// Fused kernel: per 128x32 output tile
//   phase 1: resp for 144x46 region into smem (6 warps x 24 cols, exact int)
//   phase 2: m3 = 3x3 max; prune with 9x3 max (3 m3 reads); verify survivors
//            with 5x5 stride-3 grid of m3 (exact 15x15 max); batch-emit.
// ---------------------------------------------------------------------------
#define OW 128
#define OH 32
#define RH 46
#define SR_STRIDE 144
#define M3_STRIDE 144
#define SURVCAP 256
#define WINCAP 128
#define FUSED_SMEM (RH * SR_STRIDE * 4 + 44 * M3_STRIDE * 4 + SURVCAP * 8 + WINCAP * 8 + 64)

__global__ __launch_bounds__(192) void fused_kernel(const float* __restrict__ im) {
    extern __shared__ char smem_raw[];
    float* sresp = (float*)smem_raw;                       // [RH][SR_STRIDE]
    float* m3    = sresp + RH * SR_STRIDE;                 // [44][M3_STRIDE], row i = resp row i+1
    float* sv    = m3 + 44 * M3_STRIDE;                    // [SURVCAP]
    int*   srs   = (int*)(sv + SURVCAP);                   // [SURVCAP]
    unsigned long long* wk = (unsigned long long*)(srs + SURVCAP);  // [WINCAP]
    __shared__ int scount;
    __shared__ int wcount;
    __shared__ int s_base;

    const int b  = blockIdx.z;
    const int X0 = blockIdx.x * OW;
    const int Y0 = blockIdx.y * OH;
    const int t  = threadIdx.x;
    const int wid = t >> 5, lane = t & 31;
    const int cc  = wid * 24 + lane - 4;
    const int gc  = X0 - 7 + cc;
    const bool colin   = ((unsigned)gc < W);
    const bool outlane = (lane >= 4) && (lane < 28);
    const float* imb = im + (size_t)b * HW;

    if (t == 0) { scount = 0; wcount = 0; }

    // ---- phase 1 ----
    const int y0res = Y0 - 7;
    auto loadrow = [&](int rr) -> int {
        return ((unsigned)rr < H && colin)
                   ? __float2int_rd(imb[(size_t)rr * W + gc] * 255.0f)
                   : 0;
    };

    int qm = loadrow(y0res - 4);
    int qc_ = loadrow(y0res - 3);
    int qp = loadrow(y0res - 2);
    int qn = loadrow(y0res - 1);

    int rA[7], rB[7], rC[7];
#pragma unroll
    for (int j = 0; j < 7; j++) { rA[j] = 0; rB[j] = 0; rC[j] = 0; }
    int sA = 0, sB = 0, sC = 0;

    // 56 iterations in 8 groups of 7 so ring slot k is compile-time (no shifts)
    for (int ii = 0; ii < 56; ii += 7) {
#pragma unroll
        for (int k = 0; k < 7; k++) {
            const int i = ii + k;               // i % 7 == k
            const int pr = y0res - 3 + i;
            const int qn2 = loadrow(pr + 3);

            int A = 0, Bv = 0, C = 0;
            {
                int v = qm + 2 * qc_ + qp;
                int d = qp - qm;
                int gx = __shfl_down_sync(0xffffffffu, v, 1) -
                         __shfl_up_sync(0xffffffffu, v, 1);
                int gy = __shfl_up_sync(0xffffffffu, d, 1) + 2 * d +
                         __shfl_down_sync(0xffffffffu, d, 1);
                if (((unsigned)pr < H) & colin) {
                    A = gx * gx; Bv = gx * gy; C = gy * gy;
                }
            }

            int hA, hB, hC;
            {
                int s1 = A + __shfl_down_sync(0xffffffffu, A, 1);
                int s2 = s1 + __shfl_down_sync(0xffffffffu, s1, 2);
                hA = __shfl_up_sync(0xffffffffu, s2, 3) +
                     __shfl_down_sync(0xffffffffu, s2, 1) -
                     __shfl_down_sync(0xffffffffu, A, 4);
            }
            {
                int s1 = Bv + __shfl_down_sync(0xffffffffu, Bv, 1);
                int s2 = s1 + __shfl_down_sync(0xffffffffu, s1, 2);
                hB = __shfl_up_sync(0xffffffffu, s2, 3) +
                     __shfl_down_sync(0xffffffffu, s2, 1) -
                     __shfl_down_sync(0xffffffffu, Bv, 4);
            }
            {
                int s1 = C + __shfl_down_sync(0xffffffffu, C, 1);
                int s2 = s1 + __shfl_down_sync(0xffffffffu, s1, 2);
                hC = __shfl_up_sync(0xffffffffu, s2, 3) +
                     __shfl_down_sync(0xffffffffu, s2, 1) -
                     __shfl_down_sync(0xffffffffu, C, 4);
            }

            // vertical sliding 7-sum: slot k holds h from 7 iterations ago
            sA += hA - rA[k]; rA[k] = hA;
            sB += hB - rB[k]; rB[k] = hB;
            sC += hC - rC[k]; rC[k] = hC;

            if (i >= 6 && i < RH + 6) {
                const int rr = i - 6;
                const int gr = y0res + rr;
                float fa = (float)sA, fc = (float)sC, fb = (float)sB;
                float dd = __fsub_rn(fa, fc);
                float s  = __fadd_rn(__fmul_rn(dd, dd), __fmul_rn(__fmul_rn(4.0f, fb), fb));
                float resp = 0.5f * __fsub_rn(__fadd_rn(fa, fc), __fsqrt_rn(s));
                if (outlane) {
                    float val = (((unsigned)gr < H) & colin) ? resp : -CUDART_INF_F;
                    sresp[rr * SR_STRIDE + cc] = val;
                }
            }

            qm = qc_; qc_ = qp; qp = qn; qn = qn2;
        }
    }
    __syncthreads();

    // ---- phase 2a: m3[i][cx] = 3x3 max of resp centered (i+1, cx) ----
    for (int i = t; i < 44 * 142; i += 192) {
        int mr = i / 142, cx = 1 + i % 142;      // mr = resp row - 1
        const float* p0 = &sresp[mr * SR_STRIDE + cx - 1];
        const float* p1 = p0 + SR_STRIDE;
        const float* p2 = p1 + SR_STRIDE;
        float m = fmaxf(fmaxf(fmaxf(p0[0], p0[1]), fmaxf(p0[2], p1[0])),
                        fmaxf(fmaxf(p1[1], p1[2]), fmaxf(fmaxf(p2[0], p2[1]), p2[2])));
        m3[mr * M3_STRIDE + cx] = m;
    }
    __syncthreads();

    // ---- phase 2b: prune with 9x3 max (rows r-1..r+1, cols c-4..c+4) ----
    for (int i = t; i < OH * OW; i += 192) {
        int r = 7 + (i >> 7), c = 7 + (i & 127);
        float v = sresp[r * SR_STRIDE + c];
        const float* mrow = &m3[(r - 1) * M3_STRIDE];
        float pm = fmaxf(mrow[c - 3], fmaxf(mrow[c], mrow[c + 3]));
        if (v >= pm) {
            int s = atomicAdd(&scount, 1);
            if (s < SURVCAP) { sv[s] = v; srs[s] = (r << 8) | c; }
        }
    }
    __syncthreads();

    // ---- phase 2c: verify with 5x5 stride-3 grid of m3 (exact 15x15 max) ----
    int sc = scount < SURVCAP ? scount : SURVCAP;
    for (int i = t; i < sc; i += 192) {
        float v = sv[i];
        int rc = srs[i];
        int r = rc >> 8, c = rc & 255;
        const float* mb = &m3[(r - 7) * M3_STRIDE + (c - 6)];
        float m = -CUDART_INF_F;
#pragma unroll
        for (int di = 0; di < 5; di++) {
            const float* row = mb + di * 3 * M3_STRIDE;
#pragma unroll
            for (int dj = 0; dj < 5; dj++) m = fmaxf(m, row[dj * 3]);
        }
        if (v >= m) {
            unsigned int idx = (unsigned)((Y0 + r - 7) * W + (X0 + c - 7));
            unsigned long long key =
                ((unsigned long long)ford(v) << 32) | (unsigned int)(~idx);
            int w = atomicAdd(&wcount, 1);
            if (w < WINCAP) wk[w] = key;
        }
    }
    __syncthreads();

    // ---- batch-emit winners: one global atomic per block ----
    int nw = wcount < WINCAP ? wcount : WINCAP;
    if (t == 0 && nw > 0) s_base = atomicAdd(&g_candcount[b], nw);
    __syncthreads();
    if (nw > 0) {
        int base = s_base;
        for (int i = t; i < nw; i += 192) {
            int slot = base + i;
            if (slot < CAP) g_cands[b][slot] = wk[i];
        }
    }
}

// ---------------------------------------------------------------------------
// topk: max-scan -> thresh, 6-pass histogram radix select, bitonic sort,
// threshold at output, self-reset counter.
// ---------------------------------------------------------------------------
__global__ __launch_bounds__(512) void topk_kernel(float* __restrict__ out, int write_coords) {
    const int b = blockIdx.x;
    const int t = threadIdx.x;
    __shared__ int hist[2048];
    __shared__ int s_sth[512];
    __shared__ int s_ws[16];
    __shared__ unsigned int s_mx[16];
    __shared__ unsigned long long skeys[TOPKN];
    __shared__ unsigned long long s_prefix;
    __shared__ int s_need;
    __shared__ int s_cnt;

    int n = g_candcount[b]; if (n > CAP) n = CAP;
    int Kb = n < TOPKN ? n : TOPKN;
    const unsigned long long* cb = g_cands[b];

    unsigned int hx = 0;
    for (int i = t; i < n; i += 512) {
        unsigned int hi = (unsigned int)(cb[i] >> 32);
        if (hi > hx) hx = hi;
    }
#pragma unroll
    for (int o = 16; o; o >>= 1) {
        unsigned int v = __shfl_xor_sync(0xffffffffu, hx, o);
        if (v > hx) hx = v;
    }
    if ((t & 31) == 0) s_mx[t >> 5] = hx;
    __syncthreads();
    unsigned int hmax = s_mx[0];
#pragma unroll
    for (int w = 1; w < 16; w++) if (s_mx[w] > hmax) hmax = s_mx[w];
    const float thresh = 0.3f * finv(hmax);

    unsigned long long T = 0ull;
    if (Kb > 0) {
        if (t == 0) { s_prefix = 0ull; s_need = Kb; }
        __syncthreads();
        const int sh_arr[6] = {53, 42, 31, 20, 9, 0};
#pragma unroll 1
        for (int pass = 0; pass < 6; pass++) {
            const int sh = sh_arr[pass];
            const int width = (pass < 5) ? 11 : 9;
            const unsigned int mask = (1u << width) - 1u;
            for (int i = t; i < 2048; i += 512) hist[i] = 0;
            __syncthreads();
            unsigned long long pref = s_prefix;
            const int hb = sh + width;
            const bool all = (pass == 0);
            const unsigned long long ph = all ? 0ull : (pref >> hb);
            for (int i = t; i < n; i += 512) {
                unsigned long long k = cb[i];
                if (all || (k >> hb) == ph)
                    atomicAdd(&hist[(int)((k >> sh) & mask)], 1);
            }
            __syncthreads();
            int sth = hist[4 * t] + hist[4 * t + 1] + hist[4 * t + 2] + hist[4 * t + 3];
            s_sth[t] = sth;
            int wsum = sth;
#pragma unroll
            for (int o = 16; o; o >>= 1) wsum += __shfl_xor_sync(0xffffffffu, wsum, o);
            if ((t & 31) == 0) s_ws[t >> 5] = wsum;
            __syncthreads();
            if (t == 0) {
                int need = s_need, cum = 0, w, th, bin;
                for (w = 15; w > 0; w--) { int v = s_ws[w]; if (cum + v >= need) break; cum += v; }
                for (th = 31; th > 0; th--) { int v = s_sth[w * 32 + th]; if (cum + v >= need) break; cum += v; }
                int base = (w * 32 + th) * 4;
                for (bin = 3; bin > 0; bin--) { int v = hist[base + bin]; if (cum + v >= need) break; cum += v; }
                s_need = need - cum;
                s_prefix = pref | ((unsigned long long)(base + bin) << sh);
            }
            __syncthreads();
        }
        T = s_prefix;
    }

    if (t == 0) s_cnt = 0;
    __syncthreads();
    if (Kb > 0) {
        for (int i = t; i < n; i += 512) {
            unsigned long long k = cb[i];
            if (k >= T) {
                int p = atomicAdd(&s_cnt, 1);
                if (p < TOPKN) skeys[p] = k;
            }
        }
    }
    __syncthreads();
    int m = s_cnt < TOPKN ? s_cnt : TOPKN;
    if (t >= m) skeys[t] = 0ull;
    __syncthreads();

    for (int k = 2; k <= TOPKN; k <<= 1) {
        for (int j = k >> 1; j > 0; j >>= 1) {
            int ixj = t ^ j;
            if (ixj > t) {
                unsigned long long a = skeys[t], c = skeys[ixj];
                bool sw = ((t & k) == 0) ? (a < c) : (a > c);
                if (sw) { skeys[t] = c; skeys[ixj] = a; }
            }
            __syncthreads();
        }
    }

    unsigned long long key = skeys[t];
    bool valid = (key != 0ull) && (finv((unsigned int)(key >> 32)) >= thresh);
    if (valid) {
        unsigned int idx = ~((unsigned int)key);
        out[(size_t)b * HW + idx] = 1.0f;
        if (write_coords) {
            float* coords = out + (size_t)BATCH * HW;
            coords[((size_t)b * TOPKN + t) * 2 + 0] = (float)(idx >> 10);
            coords[((size_t)b * TOPKN + t) * 2 + 1] = (float)(idx & 1023u);
        }
    } else if (write_coords) {
        float* coords = out + (size_t)BATCH * HW;
        coords[((size_t)b * TOPKN + t) * 2 + 0] = -1.0f;
        coords[((size_t)b * TOPKN + t) * 2 + 1] = -1.0f;
    }

    __syncthreads();
    if (t == 0) g_candcount[b] = 0;
}

extern "C" void kernel_launch(void* const* d_in, const int* in_sizes, int n_in,
                              void* d_out, int out_size) {
    const float* im = (const float*)d_in[0];
    float* out = (float*)d_out;

    cudaFuncSetAttribute(fused_kernel,
                         cudaFuncAttributeMaxDynamicSharedMemorySize, FUSED_SMEM);

    cudaMemsetAsync(d_out, 0, (size_t)out_size * sizeof(float));

    dim3 grid(W / OW, H / OH, BATCH);
    fused_kernel<<<grid, 192, FUSED_SMEM>>>(im);

    int wc = (out_size >= BATCH * HW + BATCH * TOPKN * 2) ? 1 : 0;
    topk_kernel<<<BATCH, 512>>>(out, wc);
}

// round 11
// speedup vs baseline: 1.1926x; 1.1230x over previous
#include <cuda_runtime.h>
#include <math_constants.h>

#define BATCH 16
#define H 1024
#define W 1024
#define HW (H * W)
#define TOPKN 512
#define CAP 131072

static __device__ float g_scores[(size_t)BATCH * HW];
static __device__ int g_ncand[BATCH];
static __device__ unsigned long long g_keys[BATCH][CAP];

__device__ __forceinline__ unsigned int ford(float f) {
    unsigned int u = __float_as_uint(f);
    return (u & 0x80000000u) ? ~u : (u | 0x80000000u);
}
__device__ __forceinline__ float finv(unsigned int u) {
    u = (u & 0x80000000u) ? (u & 0x7fffffffu) : ~u;
    return __uint_as_float(u);
}

// ===========================================================================
// K1: staged-smem Shi-Tomasi response. 32x32 tile, halo 4.
// Exact int structure tensor; bit-exact float response formula.
// ===========================================================================
__global__ __launch_bounds__(256) void k1_response(const float* __restrict__ im) {
    const int b = blockIdx.z;
    const int tx0 = blockIdx.x * 32, ty0 = blockIdx.y * 32;
    __shared__ short simg[40][42];
    __shared__ short sgx[38][40];
    __shared__ short sgy[38][40];
    __shared__ int sha[38][33];
    __shared__ int shb[38][33];
    __shared__ int shc[38][33];
    const int t = threadIdx.x;
    const float* imb = im + (size_t)b * HW;

    for (int i = t; i < 40 * 40; i += 256) {
        int r = i / 40, c = i % 40;
        int yy = ty0 - 4 + r, xx = tx0 - 4 + c;
        short v = 0;
        if ((unsigned)yy < H && (unsigned)xx < W)
            v = (short)__float2int_rd(imb[yy * W + xx] * 255.0f);
        simg[r][c] = v;
    }
    __syncthreads();

    for (int i = t; i < 38 * 38; i += 256) {
        int r = i / 38, c = i % 38;
        int yy = ty0 - 3 + r, xx = tx0 - 3 + c;
        short gx = 0, gy = 0;
        if ((unsigned)yy < H && (unsigned)xx < W) {
            int s00 = simg[r][c],     s01 = simg[r][c + 1],     s02 = simg[r][c + 2];
            int s10 = simg[r + 1][c],                           s12 = simg[r + 1][c + 2];
            int s20 = simg[r + 2][c], s21 = simg[r + 2][c + 1], s22 = simg[r + 2][c + 2];
            gx = (short)((s02 - s00) + 2 * (s12 - s10) + (s22 - s20));
            gy = (short)((s20 - s00) + 2 * (s21 - s01) + (s22 - s02));
        }
        sgx[r][c] = gx; sgy[r][c] = gy;
    }
    __syncthreads();

    for (int i = t; i < 38 * 32; i += 256) {
        int r = i / 32, c = i % 32;
        int A = 0, Bv = 0, C = 0;
#pragma unroll
        for (int d = 0; d < 7; ++d) {
            int gx = sgx[r][c + d], gy = sgy[r][c + d];
            A += gx * gx; C += gy * gy; Bv += gx * gy;
        }
        sha[r][c] = A; shb[r][c] = Bv; shc[r][c] = C;
    }
    __syncthreads();

    for (int i = t; i < 32 * 32; i += 256) {
        int r = i / 32, c = i % 32;
        int A = 0, Bv = 0, C = 0;
#pragma unroll
        for (int d = 0; d < 7; ++d) { A += sha[r + d][c]; Bv += shb[r + d][c]; C += shc[r + d][c]; }
        float fa = (float)A, fc = (float)C, fb = (float)Bv;
        float dd = __fsub_rn(fa, fc);
        float s  = __fadd_rn(__fmul_rn(dd, dd), __fmul_rn(__fmul_rn(4.0f, fb), fb));
        float resp = 0.5f * __fsub_rn(__fadd_rn(fa, fc), __fsqrt_rn(s));
        g_scores[(size_t)b * HW + (size_t)(ty0 + r) * W + (tx0 + c)] = resp;
    }
}

// ===========================================================================
// K2: pyramid NMS (15x15 max == 5x5 stride-3 grid of 3x3 maxes), then
// batch-emit winners with one global atomic per block.
// ===========================================================================
#define SURVCAP 768
#define WINCAP 64

__global__ __launch_bounds__(256) void k2_nms() {
    const int b = blockIdx.z;
    const int X0 = blockIdx.x * 32, Y0 = blockIdx.y * 32;
    __shared__ float sr[46][48];
    __shared__ float h3[46][48];
    __shared__ float m3[44][48];
    __shared__ float sv[SURVCAP];
    __shared__ int spos[SURVCAP];
    __shared__ unsigned long long wk[WINCAP];
    __shared__ int scount;
    __shared__ int wcount;
    __shared__ int s_base;
    const int t = threadIdx.x;
    const float* rbase = g_scores + (size_t)b * HW;

    if (t == 0) { scount = 0; wcount = 0; }
    for (int i = t; i < 46 * 46; i += 256) {
        int r = i / 46, c = i % 46;
        int gy = Y0 - 7 + r, gxx = X0 - 7 + c;
        sr[r][c] = ((unsigned)gy < H && (unsigned)gxx < W) ? rbase[gy * W + gxx] : -CUDART_INF_F;
    }
    __syncthreads();

    // horizontal 3-max
    for (int i = t; i < 46 * 22; i += 256) {
        int r = i / 22, x = 2 * (i % 22);
        float2 f0 = *(float2*)&sr[r][x];
        float2 f1 = *(float2*)&sr[r][x + 2];
        float h0 = fmaxf(f0.x, fmaxf(f0.y, f1.x));
        float h1 = fmaxf(f0.y, fmaxf(f1.x, f1.y));
        *(float2*)&h3[r][x] = make_float2(h0, h1);
    }
    __syncthreads();

    // vertical 3-max -> m3 (3x3 neighborhood max centered at sr[r+1][x+1])
    for (int i = t; i < 44 * 22; i += 256) {
        int r = i / 22, x = 2 * (i % 22);
        float2 a  = *(float2*)&h3[r][x];
        float2 bb = *(float2*)&h3[r + 1][x];
        float2 cc = *(float2*)&h3[r + 2][x];
        float m0 = fmaxf(a.x, fmaxf(bb.x, cc.x));
        float m1 = fmaxf(a.y, fmaxf(bb.y, cc.y));
        *(float2*)&m3[r][x] = make_float2(m0, m1);
    }
    __syncthreads();

    // prune: candidate must be >= its own 3x3 max
    for (int i = t; i < 1024; i += 256) {
        int r = i >> 5, c = i & 31;
        float v = sr[r + 7][c + 7];
        if (v >= m3[r + 6][c + 6]) {
            int s = atomicAdd(&scount, 1);
            if (s < SURVCAP) { sv[s] = v; spos[s] = (r << 5) | c; }
        }
    }
    __syncthreads();

    // verify against exact 15x15 max via 5x5 stride-3 grid of m3
    int sc = scount < SURVCAP ? scount : SURVCAP;
    for (int i = t; i < sc; i += 256) {
        float v = sv[i];
        int rc = spos[i];
        int r = rc >> 5, c = rc & 31;
        float m = -CUDART_INF_F;
#pragma unroll
        for (int di = 0; di < 5; di++)
#pragma unroll
            for (int dj = 0; dj < 5; dj++)
                m = fmaxf(m, m3[r + 3 * di][c + 3 * dj]);
        if (v >= m) {
            unsigned int idx = (unsigned)((Y0 + r) * W + (X0 + c));
            unsigned long long key =
                ((unsigned long long)ford(v) << 32) | (unsigned int)(~idx);
            int w = atomicAdd(&wcount, 1);
            if (w < WINCAP) wk[w] = key;
        }
    }
    __syncthreads();

    int nw = wcount < WINCAP ? wcount : WINCAP;
    if (t == 0 && nw > 0) s_base = atomicAdd(&g_ncand[b], nw);
    __syncthreads();
    if (nw > 0) {
        int base = s_base;
        for (int i = t; i < nw; i += 256) {
            int slot = base + i;
            if (slot < CAP) g_keys[b][slot] = wk[i];
        }
    }
}

// ===========================================================================
// K3: candidate max -> threshold; exact top-512 via 6-pass histogram radix
// select; bitonic sort; threshold applied at output; counter self-reset.
// ===========================================================================
__global__ __launch_bounds__(512) void k3_topk(float* __restrict__ out, int write_coords) {
    const int b = blockIdx.x;
    const int t = threadIdx.x;
    __shared__ int hist[2048];
    __shared__ int s_sth[512];
    __shared__ int s_ws[16];
    __shared__ unsigned int s_mx[16];
    __shared__ unsigned long long skeys[TOPKN];
    __shared__ unsigned long long s_prefix;
    __shared__ int s_need;
    __shared__ int s_cnt;

    int n = g_ncand[b]; if (n > CAP) n = CAP;
    int Kb = n < TOPKN ? n : TOPKN;
    const unsigned long long* cb = g_keys[b];

    unsigned int hx = 0;
    for (int i = t; i < n; i += 512) {
        unsigned int hi = (unsigned int)(cb[i] >> 32);
        if (hi > hx) hx = hi;
    }
#pragma unroll
    for (int o = 16; o; o >>= 1) {
        unsigned int v = __shfl_xor_sync(0xffffffffu, hx, o);
        if (v > hx) hx = v;
    }
    if ((t & 31) == 0) s_mx[t >> 5] = hx;
    __syncthreads();
    unsigned int hmax = s_mx[0];
#pragma unroll
    for (int w = 1; w < 16; w++) if (s_mx[w] > hmax) hmax = s_mx[w];
    const float thresh = 0.3f * finv(hmax);

    unsigned long long T = 0ull;
    if (Kb > 0) {
        if (t == 0) { s_prefix = 0ull; s_need = Kb; }
        __syncthreads();
        const int sh_arr[6] = {53, 42, 31, 20, 9, 0};
#pragma unroll 1
        for (int pass = 0; pass < 6; pass++) {
            const int sh = sh_arr[pass];
            const int width = (pass < 5) ? 11 : 9;
            const unsigned int mask = (1u << width) - 1u;
            for (int i = t; i < 2048; i += 512) hist[i] = 0;
            __syncthreads();
            unsigned long long pref = s_prefix;
            const int hb = sh + width;
            const bool all = (pass == 0);
            const unsigned long long ph = all ? 0ull : (pref >> hb);
            for (int i = t; i < n; i += 512) {
                unsigned long long k = cb[i];
                if (all || (k >> hb) == ph)
                    atomicAdd(&hist[(int)((k >> sh) & mask)], 1);
            }
            __syncthreads();
            int sth = hist[4 * t] + hist[4 * t + 1] + hist[4 * t + 2] + hist[4 * t + 3];
            s_sth[t] = sth;
            int wsum = sth;
#pragma unroll
            for (int o = 16; o; o >>= 1) wsum += __shfl_xor_sync(0xffffffffu, wsum, o);
            if ((t & 31) == 0) s_ws[t >> 5] = wsum;
            __syncthreads();
            if (t == 0) {
                int need = s_need, cum = 0, w, th, bin;
                for (w = 15; w > 0; w--) { int v = s_ws[w]; if (cum + v >= need) break; cum += v; }
                for (th = 31; th > 0; th--) { int v = s_sth[w * 32 + th]; if (cum + v >= need) break; cum += v; }
                int base = (w * 32 + th) * 4;
                for (bin = 3; bin > 0; bin--) { int v = hist[base + bin]; if (cum + v >= need) break; cum += v; }
                s_need = need - cum;
                s_prefix = pref | ((unsigned long long)(base + bin) << sh);
            }
            __syncthreads();
        }
        T = s_prefix;
    }

    if (t == 0) s_cnt = 0;
    __syncthreads();
    if (Kb > 0) {
        for (int i = t; i < n; i += 512) {
            unsigned long long k = cb[i];
            if (k >= T) {
                int p = atomicAdd(&s_cnt, 1);
                if (p < TOPKN) skeys[p] = k;
            }
        }
    }
    __syncthreads();
    int m = s_cnt < TOPKN ? s_cnt : TOPKN;
    if (t >= m) skeys[t] = 0ull;
    __syncthreads();

    for (int k = 2; k <= TOPKN; k <<= 1) {
        for (int j = k >> 1; j > 0; j >>= 1) {
            int ixj = t ^ j;
            if (ixj > t) {
                unsigned long long a = skeys[t], c = skeys[ixj];
                bool sw = ((t & k) == 0) ? (a < c) : (a > c);
                if (sw) { skeys[t] = c; skeys[ixj] = a; }
            }
            __syncthreads();
        }
    }

    unsigned long long key = skeys[t];
    bool valid = (key != 0ull) && (finv((unsigned int)(key >> 32)) >= thresh);
    if (valid) {
        unsigned int idx = ~((unsigned int)key);
        out[(size_t)b * HW + idx] = 1.0f;
        if (write_coords) {
            float* coords = out + (size_t)BATCH * HW;
            coords[((size_t)b * TOPKN + t) * 2 + 0] = (float)(idx >> 10);
            coords[((size_t)b * TOPKN + t) * 2 + 1] = (float)(idx & 1023u);
        }
    } else if (write_coords) {
        float* coords = out + (size_t)BATCH * HW;
        coords[((size_t)b * TOPKN + t) * 2 + 0] = -1.0f;
        coords[((size_t)b * TOPKN + t) * 2 + 1] = -1.0f;
    }

    __syncthreads();
    if (t == 0) g_ncand[b] = 0;   // self-reset so graph replay is deterministic
}

extern "C" void kernel_launch(void* const* d_in, const int* in_sizes, int n_in,
                              void* d_out, int out_size) {
    const float* im = (const float*)d_in[0];
    float* out = (float*)d_out;

    cudaMemsetAsync(d_out, 0, (size_t)out_size * sizeof(float));

    dim3 grid(W / 32, H / 32, BATCH);
    k1_response<<<grid, 256>>>(im);
    k2_nms<<<grid, 256>>>();

    int wc = (out_size >= BATCH * HW + BATCH * TOPKN * 2) ? 1 : 0;
    k3_topk<<<BATCH, 512>>>(out, wc);
}